// round 10
// baseline (speedup 1.0000x reference)
#include <cuda_runtime.h>

#define B_SZ 32
#define S_LEN 2048
#define D_MODEL 1024
#define NSTATE 256
#define LN_EPS 1e-5f

__device__ float g_u[B_SZ * S_LEN];
__device__ float g_s[B_SZ * S_LEN];

__device__ __forceinline__ float warp_sum(float v) {
    #pragma unroll
    for (int o = 16; o; o >>= 1) v += __shfl_xor_sync(0xffffffffu, v, o);
    return v;
}

// Kernel 1: u[b,s] = mean_k x[b,s,k].  One warp per row of 1024.  (at DRAM roofline)
__global__ void mean_kernel(const float* __restrict__ x) {
    int gwarp = (blockIdx.x * blockDim.x + threadIdx.x) >> 5;
    int lane  = threadIdx.x & 31;
    const float4* xp = (const float4*)(x + (size_t)gwarp * D_MODEL);
    float s = 0.f;
    #pragma unroll
    for (int k = 0; k < 8; k++) {
        float4 v = xp[lane + 32 * k];
        s += (v.x + v.y) + (v.z + v.w);
    }
    s = warp_sum(s);
    if (lane == 0) g_u[gwarp] = s * (1.0f / (float)D_MODEL);
}

// Kernel 2: sequential scan. ONE WARP HANDLES TWO BATCHES (independent chains
// interleaved to hide butterfly/rsqrt latency). 8 states/lane per batch.
// 2-step analytic lookahead, 8 channels per batch (p7,p8 merged via u1), one
// 16-channel interleaved butterfly per 2 timesteps.
__global__ void __launch_bounds__(32, 1) scan_kernel(
                            const float* __restrict__ llr,
                            const float* __restrict__ logb,
                            const float* __restrict__ cvec,
                            const float* __restrict__ logstep,
                            const float* __restrict__ lngamma,
                            const float* __restrict__ lnbeta) {
    __shared__ float su0[S_LEN + 4], su1[S_LEN + 4];
    __shared__ float ss0[S_LEN], ss1[S_LEN];
    const int b0 = 2 * blockIdx.x;
    const int b1 = b0 + 1;
    const int lane = threadIdx.x;
    const bool is0 = (lane == 0);

    // Stage both batches' u rows into SMEM; zero pads.
    {
        const float4* up0 = (const float4*)(g_u + (size_t)b0 * S_LEN);
        const float4* up1 = (const float4*)(g_u + (size_t)b1 * S_LEN);
        float4* sp0 = (float4*)su0;
        float4* sp1 = (float4*)su1;
        #pragma unroll
        for (int k = 0; k < 16; k++) {
            sp0[lane + 32 * k] = up0[lane + 32 * k];
            sp1[lane + 32 * k] = up1[lane + 32 * k];
        }
        if (lane < 4) { su0[S_LEN + lane] = 0.0f; su1[S_LEN + lane] = 0.0f; }
    }
    __syncwarp();

    const float step = expf(logstep[0]);
    // batch-independent per-state constants
    float A[8], AB[8], BD[8], GC[8];
    float pgc=0.f, pbc=0.f, pca=0.f, pca2=0.f, pgca=0.f, pcab=0.f, pcbd=0.f,
          pgcab=0.f, pgcbd=0.f, pcaab=0.f, pcabd=0.f, pab2=0.f, pabbd=0.f, pbd2=0.f;
    #pragma unroll
    for (int j = 0; j < 8; j++) {
        int i = lane + 32 * j;
        float lam = -expf(llr[i]);
        float ad  = (2.0f + step * lam) / (2.0f - step * lam);
        float bb  = expf(logb[i]);
        float bd  = step * (1.0f + ad) * bb * 0.5f;
        float g   = lngamma[i];
        float be  = lnbeta[i];
        float cc  = cvec[i];
        float a   = ad * g;
        float ab  = ad * be;
        float gc  = g * cc;
        A[j]=a; AB[j]=ab; BD[j]=bd; GC[j]=gc;
        pgc  += gc;        pbc  += be*cc;
        pca  += a;         pca2 += a*a;      pgca += gc*a;
        pcab += ab;        pcbd += bd;
        pgcab+= gc*ab;     pgcbd+= gc*bd;
        pcaab+= a*ab;      pcabd+= a*bd;
        pab2 += ab*ab;     pabbd+= ab*bd;    pbd2 += bd*bd;
    }
    const float Sgc   = warp_sum(pgc);
    const float Sbc   = warp_sum(pbc);
    const float Ca    = warp_sum(pca);
    const float Ca2   = warp_sum(pca2);
    const float Cgca  = warp_sum(pgca);
    const float Cab   = warp_sum(pcab);
    const float Cbd   = warp_sum(pcbd);
    const float Cgcab = warp_sum(pgcab);
    const float Cgcbd = warp_sum(pgcbd);
    const float Caab  = warp_sum(pcaab);
    const float Cabd  = warp_sum(pcabd);
    const float Cab2  = warp_sum(pab2);
    const float Cabbd = warp_sum(pabbd);
    const float Cbd2  = warp_sum(pbd2);

    __syncwarp();
    float za[8], zb[8];
    {
        float u0a = su0[0], u0b = su1[0];
        #pragma unroll
        for (int j = 0; j < 8; j++) { za[j] = BD[j] * u0a; zb[j] = BD[j] * u0b; }
    }

    const float invn = 1.0f / (float)NSTATE;
    for (int t = 0; t < S_LEN; t += 2) {
        float u1a = su0[t + 1], u2a = su0[t + 2];
        float u1b = su1[t + 1], u2b = su1[t + 2];

        // ── lane-local partials: 8 channels per batch (p78 merged via cst1) ──
        float c1a[8], c1b[8];
        float q0=0,q1=0,q2=0,q3=0,q4=0,q5=0,q6=0,q78=0;   // batch 0
        float r0=0,r1=0,r2=0,r3=0,r4=0,r5=0,r6=0,r78=0;   // batch 1
        #pragma unroll
        for (int j = 0; j < 8; j++) {
            float z  = za[j];
            float az = A[j] * z;
            float cc1 = fmaf(BD[j], u1a, AB[j]);   // reused in z-advance
            c1a[j] = cc1;
            q0 += z;
            q1 = fmaf(z, z, q1);
            q2 = fmaf(GC[j], z, q2);
            q3 += az;
            q4 = fmaf(A[j], az, q4);
            q5 = fmaf(az, az, q5);
            q6 = fmaf(GC[j], az, q6);
            q78 = fmaf(cc1, az, q78);              // sum (AB + u1*BD) * A * z
        }
        #pragma unroll
        for (int j = 0; j < 8; j++) {
            float z  = zb[j];
            float az = A[j] * z;
            float cc1 = fmaf(BD[j], u1b, AB[j]);
            c1b[j] = cc1;
            r0 += z;
            r1 = fmaf(z, z, r1);
            r2 = fmaf(GC[j], z, r2);
            r3 += az;
            r4 = fmaf(A[j], az, r4);
            r5 = fmaf(az, az, r5);
            r6 = fmaf(GC[j], az, r6);
            r78 = fmaf(cc1, az, r78);
        }

        // ── one interleaved 16-channel butterfly (two independent chains) ──
        #pragma unroll
        for (int o = 16; o; o >>= 1) {
            q0  += __shfl_xor_sync(0xffffffffu, q0,  o);
            r0  += __shfl_xor_sync(0xffffffffu, r0,  o);
            q1  += __shfl_xor_sync(0xffffffffu, q1,  o);
            r1  += __shfl_xor_sync(0xffffffffu, r1,  o);
            q2  += __shfl_xor_sync(0xffffffffu, q2,  o);
            r2  += __shfl_xor_sync(0xffffffffu, r2,  o);
            q3  += __shfl_xor_sync(0xffffffffu, q3,  o);
            r3  += __shfl_xor_sync(0xffffffffu, r3,  o);
            q4  += __shfl_xor_sync(0xffffffffu, q4,  o);
            r4  += __shfl_xor_sync(0xffffffffu, r4,  o);
            q5  += __shfl_xor_sync(0xffffffffu, q5,  o);
            r5  += __shfl_xor_sync(0xffffffffu, r5,  o);
            q6  += __shfl_xor_sync(0xffffffffu, q6,  o);
            r6  += __shfl_xor_sync(0xffffffffu, r6,  o);
            q78 += __shfl_xor_sync(0xffffffffu, q78, o);
            r78 += __shfl_xor_sync(0xffffffffu, r78, o);
        }

        // ── batch 0 scalar stage ──
        float mua  = q0 * invn;
        float vara = fmaf(q1, invn, -mua * mua);
        float rsa  = rsqrtf(vara + LN_EPS);
        float T2a  = fmaf(mua * mua, Ca2, fmaf(-2.0f * mua, q4, q5));
        float T1a  = q78 - mua * fmaf(u1a, Cabd, Caab);
        float T0a  = fmaf(u1a * u1a, Cbd2, fmaf(2.0f * u1a, Cabbd, Cab2));
        float S1na = fmaf(rsa, fmaf(-mua, Ca, q3), fmaf(Cbd, u1a, Cab));
        float S3na = fmaf(rsa, fmaf(-mua, Cgca, q6), fmaf(Cgcbd, u1a, Cgcab));
        float S2na = fmaf(rsa * rsa, T2a, fmaf(2.0f * rsa, T1a, T0a));
        float muna  = S1na * invn;
        float varna = fmaf(S2na, invn, -muna * muna);
        float rsna  = rsqrtf(varna + LN_EPS);

        // ── batch 1 scalar stage (independent — overlaps batch 0's rsqrt) ──
        float mub  = r0 * invn;
        float varb = fmaf(r1, invn, -mub * mub);
        float rsb  = rsqrtf(varb + LN_EPS);
        float T2b  = fmaf(mub * mub, Ca2, fmaf(-2.0f * mub, r4, r5));
        float T1b  = r78 - mub * fmaf(u1b, Cabd, Caab);
        float T0b  = fmaf(u1b * u1b, Cbd2, fmaf(2.0f * u1b, Cabbd, Cab2));
        float S1nb = fmaf(rsb, fmaf(-mub, Ca, r3), fmaf(Cbd, u1b, Cab));
        float S3nb = fmaf(rsb, fmaf(-mub, Cgca, r6), fmaf(Cgcbd, u1b, Cgcab));
        float S2nb = fmaf(rsb * rsb, T2b, fmaf(2.0f * rsb, T1b, T0b));
        float munb  = S1nb * invn;
        float varnb = fmaf(S2nb, invn, -munb * munb);
        float rsnb  = rsqrtf(varnb + LN_EPS);

        if (is0) {
            ss0[t]     = fmaf(rsa,  fmaf(-mua,  Sgc, q2),   Sbc);
            ss0[t + 1] = fmaf(rsna, fmaf(-muna, Sgc, S3na), Sbc);
            ss1[t]     = fmaf(rsb,  fmaf(-mub,  Sgc, r2),   Sbc);
            ss1[t + 1] = fmaf(rsnb, fmaf(-munb, Sgc, S3nb), Sbc);
        }

        // ── advance both batches' z two steps (exact, independent chains) ──
        float g1a = -rsa * mua,  gna = -rsna * muna;
        float g1b = -rsb * mub,  gnb = -rsnb * munb;
        #pragma unroll
        for (int j = 0; j < 8; j++) {
            float wa  = fmaf(za[j], rsa, g1a);
            float z1a = fmaf(wa, A[j], c1a[j]);
            float w2a = fmaf(z1a, rsna, gna);
            za[j]     = fmaf(w2a, A[j], fmaf(BD[j], u2a, AB[j]));

            float wb  = fmaf(zb[j], rsb, g1b);
            float z1b = fmaf(wb, A[j], c1b[j]);
            float w2b = fmaf(z1b, rsnb, gnb);
            zb[j]     = fmaf(w2b, A[j], fmaf(BD[j], u2b, AB[j]));
        }
    }

    __syncwarp();
    {
        float4* gp0 = (float4*)(g_s + (size_t)b0 * S_LEN);
        float4* gp1 = (float4*)(g_s + (size_t)b1 * S_LEN);
        const float4* sp0 = (const float4*)ss0;
        const float4* sp1 = (const float4*)ss1;
        #pragma unroll
        for (int k = 0; k < 16; k++) {
            gp0[lane + 32 * k] = sp0[lane + 32 * k];
            gp1[lane + 32 * k] = sp1[lane + 32 * k];
        }
    }
}

// Kernel 3: out[b,s,:] = c1 * x[b,s,:] + c2 * s[b,s]   (at DRAM roofline)
__global__ void out_kernel(const float* __restrict__ x,
                           const float* __restrict__ alpha,
                           const float* __restrict__ logd,
                           float* __restrict__ out) {
    const int row = blockIdx.x;
    const int tid = threadIdx.x;
    float a_sig = 1.0f / (1.0f + expf(-alpha[0]));
    float dd = expf(logd[0]);
    float c1 = a_sig + (1.0f - a_sig) * dd;
    float c2s = (1.0f - a_sig) * g_s[row];

    const float4* xp = (const float4*)(x + (size_t)row * D_MODEL);
    float4* op = (float4*)(out + (size_t)row * D_MODEL);
    float4 v = xp[tid];
    v.x = fmaf(c1, v.x, c2s);
    v.y = fmaf(c1, v.y, c2s);
    v.z = fmaf(c1, v.z, c2s);
    v.w = fmaf(c1, v.w, c2s);
    op[tid] = v;
}

extern "C" void kernel_launch(void* const* d_in, const int* in_sizes, int n_in,
                              void* d_out, int out_size) {
    const float* x        = (const float*)d_in[0];
    const float* llr      = (const float*)d_in[1];
    const float* logb     = (const float*)d_in[2];
    const float* cvec     = (const float*)d_in[3];
    const float* logd     = (const float*)d_in[4];
    const float* logstep  = (const float*)d_in[5];
    const float* alpha    = (const float*)d_in[6];
    const float* lngamma  = (const float*)d_in[7];
    const float* lnbeta   = (const float*)d_in[8];
    float* out = (float*)d_out;

    mean_kernel<<<(B_SZ * S_LEN) / 8, 256>>>(x);
    scan_kernel<<<B_SZ / 2, 32>>>(llr, logb, cvec, logstep, lngamma, lnbeta);
    out_kernel<<<B_SZ * S_LEN, 256>>>(x, alpha, logd, out);
}

// round 11
// speedup vs baseline: 1.2040x; 1.2040x over previous
#include <cuda_runtime.h>

#define B_SZ 32
#define S_LEN 2048
#define D_MODEL 1024
#define NSTATE 256
#define LN_EPS 1e-5f

__device__ float g_u[B_SZ * S_LEN];
__device__ float g_s[B_SZ * S_LEN];

__device__ __forceinline__ float warp_sum(float v) {
    #pragma unroll
    for (int o = 16; o; o >>= 1) v += __shfl_xor_sync(0xffffffffu, v, o);
    return v;
}

// Kernel 1: u[b,s] = mean_k x[b,s,k].  One warp per row of 1024.  (at DRAM roofline)
__global__ void mean_kernel(const float* __restrict__ x) {
    int gwarp = (blockIdx.x * blockDim.x + threadIdx.x) >> 5;
    int lane  = threadIdx.x & 31;
    const float4* xp = (const float4*)(x + (size_t)gwarp * D_MODEL);
    float s = 0.f;
    #pragma unroll
    for (int k = 0; k < 8; k++) {
        float4 v = xp[lane + 32 * k];
        s += (v.x + v.y) + (v.z + v.w);
    }
    s = warp_sum(s);
    if (lane == 0) g_u[gwarp] = s * (1.0f / (float)D_MODEL);
}

// Kernel 2: sequential scan, TWO WARPS per batch (different SMSPs) splitting the
// issue-bound instruction stream. Each warp owns 128 states (4/lane).
// 2-step analytic lookahead, 8 channels; channel-split butterfly (4 per warp);
// SMEM exchange with parity double-buffering; scalar stage duplicated.
__global__ void __launch_bounds__(64, 1) scan_kernel(
                            const float* __restrict__ llr,
                            const float* __restrict__ logb,
                            const float* __restrict__ cvec,
                            const float* __restrict__ logstep,
                            const float* __restrict__ lngamma,
                            const float* __restrict__ lnbeta) {
    __shared__ float su[S_LEN + 4];
    __shared__ float ss[S_LEN];
    __shared__ float P[2][8][32];    // partial-vector exchange (parity buffered)
    __shared__ float R[2][8];        // reduced-sum exchange

    const int b    = blockIdx.x;
    const int tid  = threadIdx.x;
    const int w    = tid >> 5;       // 0 or 1 -> SMSP 0 / 1
    const int lane = tid & 31;

    // Stage this batch's u row into SMEM; zero pad.
    {
        const float4* up = (const float4*)(g_u + (size_t)b * S_LEN);
        float4* sp = (float4*)su;
        #pragma unroll
        for (int k = 0; k < 8; k++) sp[tid + 64 * k] = up[tid + 64 * k];
        if (tid < 4) su[S_LEN + tid] = 0.0f;
    }

    // Prologue: each warp independently computes the 14 global constants over ALL
    // 256 states (redundant, prologue-only); keeps per-state arrays for OWN 128.
    const float step = expf(logstep[0]);
    float A[4], AB[4], BD[4], GC[4], z[4];
    float pgc=0.f, pbc=0.f, pca=0.f, pca2=0.f, pgca=0.f, pcab=0.f, pcbd=0.f,
          pgcab=0.f, pgcbd=0.f, pcaab=0.f, pcabd=0.f, pab2=0.f, pabbd=0.f, pbd2=0.f;
    #pragma unroll
    for (int j = 0; j < 8; j++) {
        int i = lane + 32 * j;
        float lam = -expf(llr[i]);
        float ad  = (2.0f + step * lam) / (2.0f - step * lam);
        float bb  = expf(logb[i]);
        float bd  = step * (1.0f + ad) * bb * 0.5f;
        float g   = lngamma[i];
        float be  = lnbeta[i];
        float cc  = cvec[i];
        float a   = ad * g;
        float ab  = ad * be;
        float gc  = g * cc;
        if ((j >> 2) == w) {          // own state -> keep
            int jj = j & 3;
            A[jj]=a; AB[jj]=ab; BD[jj]=bd; GC[jj]=gc;
        }
        pgc  += gc;        pbc  += be*cc;
        pca  += a;         pca2 += a*a;      pgca += gc*a;
        pcab += ab;        pcbd += bd;
        pgcab+= gc*ab;     pgcbd+= gc*bd;
        pcaab+= a*ab;      pcabd+= a*bd;
        pab2 += ab*ab;     pabbd+= ab*bd;    pbd2 += bd*bd;
    }
    const float Sgc   = warp_sum(pgc);
    const float Sbc   = warp_sum(pbc);
    const float Ca    = warp_sum(pca);
    const float Ca2   = warp_sum(pca2);
    const float Cgca  = warp_sum(pgca);
    const float Cab   = warp_sum(pcab);
    const float Cbd   = warp_sum(pcbd);
    const float Cgcab = warp_sum(pgcab);
    const float Cgcbd = warp_sum(pgcbd);
    const float Caab  = warp_sum(pcaab);
    const float Cabd  = warp_sum(pcabd);
    const float Cab2  = warp_sum(pab2);
    const float Cabbd = warp_sum(pabbd);
    const float Cbd2  = warp_sum(pbd2);

    __syncthreads();
    {
        float u0 = su[0];
        #pragma unroll
        for (int j = 0; j < 4; j++) z[j] = BD[j] * u0;   // h0 = 0
    }

    const float invn = 1.0f / (float)NSTATE;
    for (int t = 0; t < S_LEN; t += 2) {
        const int par = (t >> 1) & 1;
        float u1 = su[t + 1], u2 = su[t + 2];

        // ── 8-channel lane partials over OWN 4 states ──
        float c1s[4];
        float q0=0,q1=0,q2=0,q3=0,q4=0,q5=0,q6=0,q78=0;
        #pragma unroll
        for (int j = 0; j < 4; j++) {
            float zz = z[j];
            float az = A[j] * zz;
            float cc1 = fmaf(BD[j], u1, AB[j]);
            c1s[j] = cc1;
            q0 += zz;
            q1 = fmaf(zz, zz, q1);
            q2 = fmaf(GC[j], zz, q2);
            q3 += az;
            q4 = fmaf(A[j], az, q4);
            q5 = fmaf(az, az, q5);
            q6 = fmaf(GC[j], az, q6);
            q78 = fmaf(cc1, az, q78);
        }

        // ── ship non-owned channels to the other warp ──
        if (w == 0) {
            P[par][4][lane] = q4;  P[par][5][lane] = q5;
            P[par][6][lane] = q6;  P[par][7][lane] = q78;
        } else {
            P[par][0][lane] = q0;  P[par][1][lane] = q1;
            P[par][2][lane] = q2;  P[par][3][lane] = q3;
        }
        __syncthreads();

        // ── merge + butterfly own 4 channels; publish reduced sums ──
        if (w == 0) {
            q0 += P[par][0][lane];  q1 += P[par][1][lane];
            q2 += P[par][2][lane];  q3 += P[par][3][lane];
            #pragma unroll
            for (int o = 16; o; o >>= 1) {
                q0 += __shfl_xor_sync(0xffffffffu, q0, o);
                q1 += __shfl_xor_sync(0xffffffffu, q1, o);
                q2 += __shfl_xor_sync(0xffffffffu, q2, o);
                q3 += __shfl_xor_sync(0xffffffffu, q3, o);
            }
            if (lane == 0) *(float4*)&R[par][0] = make_float4(q0, q1, q2, q3);
        } else {
            q4 += P[par][4][lane];  q5 += P[par][5][lane];
            q6 += P[par][6][lane];  q78 += P[par][7][lane];
            #pragma unroll
            for (int o = 16; o; o >>= 1) {
                q4  += __shfl_xor_sync(0xffffffffu, q4,  o);
                q5  += __shfl_xor_sync(0xffffffffu, q5,  o);
                q6  += __shfl_xor_sync(0xffffffffu, q6,  o);
                q78 += __shfl_xor_sync(0xffffffffu, q78, o);
            }
            if (lane == 0) *(float4*)&R[par][4] = make_float4(q4, q5, q6, q78);
        }
        __syncthreads();

        // fetch the other half of reduced sums (uniform broadcast LDS.128)
        if (w == 0) {
            float4 r = *(const float4*)&R[par][4];
            q4 = r.x; q5 = r.y; q6 = r.z; q78 = r.w;
        } else {
            float4 r = *(const float4*)&R[par][0];
            q0 = r.x; q1 = r.y; q2 = r.z; q3 = r.w;
        }

        // ── scalar stage (identical in both warps; full sums) ──
        float mu  = q0 * invn;
        float var = fmaf(q1, invn, -mu * mu);
        float rs  = rsqrtf(var + LN_EPS);
        float T2  = fmaf(mu * mu, Ca2, fmaf(-2.0f * mu, q4, q5));
        float T1  = q78 - mu * fmaf(u1, Cabd, Caab);
        float T0  = fmaf(u1 * u1, Cbd2, fmaf(2.0f * u1, Cabbd, Cab2));
        float S1n = fmaf(rs, fmaf(-mu, Ca, q3), fmaf(Cbd, u1, Cab));
        float S3n = fmaf(rs, fmaf(-mu, Cgca, q6), fmaf(Cgcbd, u1, Cgcab));
        float S2n = fmaf(rs * rs, T2, fmaf(2.0f * rs, T1, T0));
        float mun  = S1n * invn;
        float varn = fmaf(S2n, invn, -mun * mun);
        float rsn  = rsqrtf(varn + LN_EPS);

        if (tid == 0) {
            ss[t]     = fmaf(rs,  fmaf(-mu,  Sgc, q2),  Sbc);
            ss[t + 1] = fmaf(rsn, fmaf(-mun, Sgc, S3n), Sbc);
        }

        // ── advance own 4 states two steps (exact) ──
        float g1v = -rs * mu;
        float gnv = -rsn * mun;
        #pragma unroll
        for (int j = 0; j < 4; j++) {
            float ww  = fmaf(z[j], rs, g1v);
            float z1  = fmaf(ww, A[j], c1s[j]);
            float w2  = fmaf(z1, rsn, gnv);
            z[j]      = fmaf(w2, A[j], fmaf(BD[j], u2, AB[j]));
        }
    }

    __syncthreads();
    {
        float4* gp = (float4*)(g_s + (size_t)b * S_LEN);
        const float4* sp = (const float4*)ss;
        #pragma unroll
        for (int k = 0; k < 8; k++) gp[tid + 64 * k] = sp[tid + 64 * k];
    }
}

// Kernel 3: out[b,s,:] = c1 * x[b,s,:] + c2 * s[b,s]   (at DRAM roofline)
__global__ void out_kernel(const float* __restrict__ x,
                           const float* __restrict__ alpha,
                           const float* __restrict__ logd,
                           float* __restrict__ out) {
    const int row = blockIdx.x;
    const int tid = threadIdx.x;
    float a_sig = 1.0f / (1.0f + expf(-alpha[0]));
    float dd = expf(logd[0]);
    float c1 = a_sig + (1.0f - a_sig) * dd;
    float c2s = (1.0f - a_sig) * g_s[row];

    const float4* xp = (const float4*)(x + (size_t)row * D_MODEL);
    float4* op = (float4*)(out + (size_t)row * D_MODEL);
    float4 v = xp[tid];
    v.x = fmaf(c1, v.x, c2s);
    v.y = fmaf(c1, v.y, c2s);
    v.z = fmaf(c1, v.z, c2s);
    v.w = fmaf(c1, v.w, c2s);
    op[tid] = v;
}

extern "C" void kernel_launch(void* const* d_in, const int* in_sizes, int n_in,
                              void* d_out, int out_size) {
    const float* x        = (const float*)d_in[0];
    const float* llr      = (const float*)d_in[1];
    const float* logb     = (const float*)d_in[2];
    const float* cvec     = (const float*)d_in[3];
    const float* logd     = (const float*)d_in[4];
    const float* logstep  = (const float*)d_in[5];
    const float* alpha    = (const float*)d_in[6];
    const float* lngamma  = (const float*)d_in[7];
    const float* lnbeta   = (const float*)d_in[8];
    float* out = (float*)d_out;

    mean_kernel<<<(B_SZ * S_LEN) / 8, 256>>>(x);
    scan_kernel<<<B_SZ, 64>>>(llr, logb, cvec, logstep, lngamma, lnbeta);
    out_kernel<<<B_SZ * S_LEN, 256>>>(x, alpha, logd, out);
}